// round 12
// baseline (speedup 1.0000x reference)
#include <cuda_runtime.h>
#include <cuda_bf16.h>
#include <cstdint>

#define M_DIM 8192
#define K_DIM 4096
#define N_DIM 16384

#define BM 128
#define BN 256
#define BKE 64                     // K elements per stage (bf16) = 128B rows
#define NKT (K_DIM / BKE)          // 64
#define NS 4
#define STG_A (BM * 128)           // 16384 bytes
#define STG_B (BN * 128)           // 32768 bytes
#define STG (STG_A + STG_B)        // 49152
#define SMEM_TOTAL (NS * STG + 1024 + 128)

// Tiled, pre-swizzled bf16 operand images (device globals; allocation-free rule)
static __device__ __align__(128) __nv_bfloat16 g_qa[(size_t)M_DIM * K_DIM];  // 64 MB
static __device__ __align__(128) __nv_bfloat16 g_wb[(size_t)N_DIM * K_DIM];  // 128 MB
static __device__ float g_sx[M_DIM];

// ---------------------------------------------------------------------------
// Kernel 1: per-row absmax + int8 quantization -> bf16 (exact for |q|<=127),
// tile-major swizzled image: g_qa blocks [tm][kt], 128 rows x 128B.
// ---------------------------------------------------------------------------
__global__ void quant_rows_kernel(const float* __restrict__ x) {
    int row = blockIdx.x;
    int t = threadIdx.x;
    const float4* xr = reinterpret_cast<const float4*>(x + (size_t)row * K_DIM);
    float4 v[4];
    float amax = 0.0f;
#pragma unroll
    for (int i = 0; i < 4; i++) {
        v[i] = xr[t * 4 + i];
        amax = fmaxf(amax, fabsf(v[i].x));
        amax = fmaxf(amax, fabsf(v[i].y));
        amax = fmaxf(amax, fabsf(v[i].z));
        amax = fmaxf(amax, fabsf(v[i].w));
    }
    __shared__ float red[8];
    __shared__ float s_scale;
#pragma unroll
    for (int o = 16; o > 0; o >>= 1)
        amax = fmaxf(amax, __shfl_xor_sync(0xffffffffu, amax, o));
    if ((t & 31) == 0) red[t >> 5] = amax;
    __syncthreads();
    if (t == 0) {
        float m = red[0];
#pragma unroll
        for (int i = 1; i < 8; i++) m = fmaxf(m, red[i]);
        float sc = m / 127.0f;
        s_scale = sc;
        g_sx[row] = sc;
    }
    __syncthreads();
    float scale = s_scale;

    union { __nv_bfloat16 h[16]; int4 i4[2]; } q;
#pragma unroll
    for (int i = 0; i < 4; i++) {
        q.h[i * 4 + 0] = __float2bfloat16_rn((float)__float2int_rn(v[i].x / scale));
        q.h[i * 4 + 1] = __float2bfloat16_rn((float)__float2int_rn(v[i].y / scale));
        q.h[i * 4 + 2] = __float2bfloat16_rn((float)__float2int_rn(v[i].z / scale));
        q.h[i * 4 + 3] = __float2bfloat16_rn((float)__float2int_rn(v[i].w / scale));
    }
    int tm = row >> 7, lrow = row & 127;
    int kt = t >> 2;
    int ch0 = (t & 3) * 2;
    char* blk = (char*)g_qa + (((size_t)tm * NKT + kt) << 14) + (size_t)lrow * 128;
    *reinterpret_cast<int4*>(blk + (((ch0)     ^ (lrow & 7)) << 4)) = q.i4[0];
    *reinterpret_cast<int4*>(blk + (((ch0 + 1) ^ (lrow & 7)) << 4)) = q.i4[1];
}

// ---------------------------------------------------------------------------
// Kernel 2: int32 weights -> bf16 (exact), tile-major swizzled image:
// g_wb blocks [tn][kt] of 256 rows x 128 bytes (BN=256 tiling).
// ---------------------------------------------------------------------------
__global__ void convert_w_kernel(const int* __restrict__ w) {
    int n = blockIdx.x;
    int t = threadIdx.x;
    const int4* wr = reinterpret_cast<const int4*>(w + (size_t)n * K_DIM);
    union { __nv_bfloat16 h[16]; int4 i4[2]; } q;
#pragma unroll
    for (int i = 0; i < 4; i++) {
        int4 v = wr[t * 4 + i];
        q.h[i * 4 + 0] = __float2bfloat16_rn((float)v.x);
        q.h[i * 4 + 1] = __float2bfloat16_rn((float)v.y);
        q.h[i * 4 + 2] = __float2bfloat16_rn((float)v.z);
        q.h[i * 4 + 3] = __float2bfloat16_rn((float)v.w);
    }
    int tn = n >> 8, lrow = n & 255;
    int kt = t >> 2;
    int ch0 = (t & 3) * 2;
    char* blk = (char*)g_wb + (((size_t)tn * NKT + kt) << 15) + (size_t)lrow * 128;
    *reinterpret_cast<int4*>(blk + (((ch0)     ^ (lrow & 7)) << 4)) = q.i4[0];
    *reinterpret_cast<int4*>(blk + (((ch0 + 1) ^ (lrow & 7)) << 4)) = q.i4[1];
}

// ---------------------------------------------------------------------------
// Kernel 3: bf16 HMMA GEMM, CTA tile 128x256, 16 warps (warp tile 32x64,
// 4M x 4N grid), NS=4 bulk-copy mbarrier pipeline, 512 threads, 1 CTA/SM.
// Crossbar drops to ~47% of floor -> HMMA is the only binding pipe.
// ---------------------------------------------------------------------------
__device__ __forceinline__ uint32_t smem_u32(const void* p) {
    uint32_t a;
    asm("{ .reg .u64 t; cvta.to.shared.u64 t, %1; cvt.u32.u64 %0, t; }" : "=r"(a) : "l"(p));
    return a;
}
__device__ __forceinline__ void mbar_init(uint32_t a, uint32_t c) {
    asm volatile("mbarrier.init.shared.b64 [%0], %1;" :: "r"(a), "r"(c) : "memory");
}
__device__ __forceinline__ void mbar_expect_tx(uint32_t a, uint32_t tx) {
    asm volatile("mbarrier.arrive.expect_tx.shared::cta.b64 _, [%0], %1;"
                 :: "r"(a), "r"(tx) : "memory");
}
__device__ __forceinline__ void bulk_g2s(uint32_t dst, const void* src, uint32_t bytes,
                                         uint32_t mbar) {
    asm volatile(
        "cp.async.bulk.shared::cta.global.mbarrier::complete_tx::bytes [%0], [%1], %2, [%3];"
        :: "r"(dst), "l"(src), "r"(bytes), "r"(mbar) : "memory");
}
__device__ __forceinline__ void mbar_wait(uint32_t a, uint32_t ph) {
    asm volatile(
        "{\n .reg .pred P;\n"
        "WL_%=:\n"
        " mbarrier.try_wait.parity.acquire.cta.shared::cta.b64 P, [%0], %1;\n"
        " @P bra.uni WD_%=;\n"
        " bra.uni WL_%=;\n"
        "WD_%=:\n}" :: "r"(a), "r"(ph) : "memory");
}
__device__ __forceinline__ void ldm_x4(uint32_t& r0, uint32_t& r1, uint32_t& r2,
                                       uint32_t& r3, uint32_t addr) {
    asm volatile("ldmatrix.sync.aligned.m8n8.x4.shared.b16 {%0,%1,%2,%3}, [%4];"
                 : "=r"(r0), "=r"(r1), "=r"(r2), "=r"(r3) : "r"(addr));
}

__global__ __launch_bounds__(512, 1) void gemm_hmma_kernel(const float* __restrict__ wscale,
                                                           const float* __restrict__ bias,
                                                           float* __restrict__ out) {
    extern __shared__ char smem[];
    uint32_t raw = smem_u32(smem);
    uint32_t sbase = (raw + 1023u) & ~1023u;
    uint32_t fullb = sbase + NS * STG;            // NS x 8B

    const int t = threadIdx.x;
    const int wid = t >> 5;
    const int lane = t & 31;
    const int warpM = wid & 3;                    // 4 warps along M (32 rows each)
    const int warpN = wid >> 2;                   // 4 warps along N (64 cols each)

    // tile decode with L2 group swizzle: tiles_m=64, tiles_n=64, GM=8
    int gid = blockIdx.x;
    int grp = gid >> 9;
    int rem = gid & 511;
    int tm = grp * 8 + (rem & 7);
    int tn = rem >> 3;

    const char* gA = (const char*)g_qa + ((size_t)tm * NKT << 14);
    const char* gB = (const char*)g_wb + ((size_t)tn * NKT << 15);

    if (t == 0) {
#pragma unroll
        for (int s = 0; s < NS; s++) mbar_init(fullb + 8 * s, 1);
    }
    __syncthreads();

    auto issue = [&](int buf, int kt) {
        uint32_t mb = fullb + 8 * buf;
        mbar_expect_tx(mb, STG);
        bulk_g2s(sbase + buf * STG,         gA + ((size_t)kt << 14), STG_A, mb);
        bulk_g2s(sbase + buf * STG + STG_A, gB + ((size_t)kt << 15), STG_B, mb);
    };

    if (t == 0) {
        issue(0, 0);
        issue(1, 1);
        issue(2, 2);
    }

    float acc[2][8][4];
#pragma unroll
    for (int mf = 0; mf < 2; mf++)
#pragma unroll
        for (int nf = 0; nf < 8; nf++)
#pragma unroll
            for (int i = 0; i < 4; i++) acc[mf][nf][i] = 0.0f;

    const int seg = lane >> 3;
    const int lrow = lane & 7;
    const int a_rb = warpM * 32 + (seg & 1) * 8 + lrow;    // + mf*16
    const int b_rb = warpN * 64 + (seg & 1) * 8 + lrow;    // + nf2*16
    const int cseg = seg >> 1;

    int s = 0, ph = 0;
    for (int kt = 0; kt < NKT; kt++) {
        mbar_wait(fullb + 8 * s, ph);

        uint32_t sA = sbase + s * STG;
        uint32_t sB = sA + STG_A;

#pragma unroll
        for (int ks = 0; ks < 4; ks++) {
            const int chunk = cseg + 2 * ks;
            uint32_t a[2][4], b[8][2];
#pragma unroll
            for (int mf = 0; mf < 2; mf++) {
                int r = a_rb + mf * 16;
                ldm_x4(a[mf][0], a[mf][1], a[mf][2], a[mf][3],
                       sA + r * 128 + ((chunk ^ (r & 7)) << 4));
            }
#pragma unroll
            for (int nf2 = 0; nf2 < 4; nf2++) {
                int r = b_rb + nf2 * 16;
                uint32_t r0, r1, r2, r3;
                ldm_x4(r0, r1, r2, r3, sB + r * 128 + ((chunk ^ (r & 7)) << 4));
                b[nf2 * 2][0] = r0; b[nf2 * 2][1] = r2;
                b[nf2 * 2 + 1][0] = r1; b[nf2 * 2 + 1][1] = r3;
            }
#pragma unroll
            for (int mf = 0; mf < 2; mf++)
#pragma unroll
                for (int nf = 0; nf < 8; nf++)
                    asm volatile(
                        "mma.sync.aligned.m16n8k16.row.col.f32.bf16.bf16.f32 "
                        "{%0,%1,%2,%3}, {%4,%5,%6,%7}, {%8,%9}, {%0,%1,%2,%3};\n"
                        : "+f"(acc[mf][nf][0]), "+f"(acc[mf][nf][1]),
                          "+f"(acc[mf][nf][2]), "+f"(acc[mf][nf][3])
                        : "r"(a[mf][0]), "r"(a[mf][1]), "r"(a[mf][2]), "r"(a[mf][3]),
                          "r"(b[nf][0]), "r"(b[nf][1]));
        }

        __syncthreads();
        int nk = kt + NS - 1;
        if (t == 0 && nk < NKT) issue(s == 0 ? NS - 1 : s - 1, nk);
        if (++s == NS) { s = 0; ph ^= 1; }
    }

    // epilogue: dequant + bias (nf outer: scale/bias loaded once per column pair)
    const int tig = lane & 3;
    const int gID = lane >> 2;
    int rbase = tm * BM + warpM * 32 + gID;
    float sx00 = __ldg(g_sx + rbase);
    float sx01 = __ldg(g_sx + rbase + 8);
    float sx10 = __ldg(g_sx + rbase + 16);
    float sx11 = __ldg(g_sx + rbase + 24);
    float* orow = out + (size_t)rbase * N_DIM + tn * BN;
#pragma unroll
    for (int nf = 0; nf < 8; nf++) {
        int c = warpN * 64 + nf * 8 + tig * 2;
        float w0 = __ldg(wscale + tn * BN + c);
        float w1 = __ldg(wscale + tn * BN + c + 1);
        float b0 = __ldg(bias + tn * BN + c);
        float b1 = __ldg(bias + tn * BN + c + 1);
        float2 v;
        v.x = acc[0][nf][0] * sx00 * w0 + b0;
        v.y = acc[0][nf][1] * sx00 * w1 + b1;
        *(float2*)(orow + c) = v;
        v.x = acc[0][nf][2] * sx01 * w0 + b0;
        v.y = acc[0][nf][3] * sx01 * w1 + b1;
        *(float2*)(orow + (size_t)8 * N_DIM + c) = v;
        v.x = acc[1][nf][0] * sx10 * w0 + b0;
        v.y = acc[1][nf][1] * sx10 * w1 + b1;
        *(float2*)(orow + (size_t)16 * N_DIM + c) = v;
        v.x = acc[1][nf][2] * sx11 * w0 + b0;
        v.y = acc[1][nf][3] * sx11 * w1 + b1;
        *(float2*)(orow + (size_t)24 * N_DIM + c) = v;
    }
}

// ---------------------------------------------------------------------------
extern "C" void kernel_launch(void* const* d_in, const int* in_sizes, int n_in,
                              void* d_out, int out_size) {
    (void)in_sizes; (void)n_in; (void)out_size;
    const float* x      = (const float*)d_in[0];
    const int*   wq     = (const int*)d_in[1];
    const float* wscale = (const float*)d_in[2];
    const float* bias   = (const float*)d_in[3];
    float* out = (float*)d_out;

    quant_rows_kernel<<<M_DIM, 256>>>(x);
    convert_w_kernel<<<N_DIM, 256>>>(wq);

    cudaFuncSetAttribute(gemm_hmma_kernel, cudaFuncAttributeMaxDynamicSharedMemorySize,
                         SMEM_TOTAL);
    int gemm_blocks = (M_DIM / BM) * (N_DIM / BN);   // 64 * 64 = 4096
    gemm_hmma_kernel<<<gemm_blocks, 512, SMEM_TOTAL>>>(wscale, bias, out);
}

// round 13
// speedup vs baseline: 1.0961x; 1.0961x over previous
#include <cuda_runtime.h>
#include <cuda_bf16.h>
#include <cstdint>

#define M_DIM 8192
#define K_DIM 4096
#define N_DIM 16384

#define BM 128
#define BN 128
#define BKE 64                     // K elements per stage (bf16) = 128B rows
#define NKT (K_DIM / BKE)          // 64
#define NS 3
#define STG_A (BM * 128)           // 16384 bytes
#define STG_B (BN * 128)           // 16384 bytes
#define STG (STG_A + STG_B)        // 32768
#define SMEM_TOTAL (NS * STG + 1024 + 128)

// Tiled, pre-swizzled bf16 operand images (device globals; allocation-free rule)
static __device__ __align__(128) __nv_bfloat16 g_qa[(size_t)M_DIM * K_DIM];  // 64 MB
static __device__ __align__(128) __nv_bfloat16 g_wb[(size_t)N_DIM * K_DIM];  // 128 MB
static __device__ float g_sx[M_DIM];

// ---------------------------------------------------------------------------
// Kernel 1 (merged): blocks [0, M_DIM) do per-row activation quantization;
// blocks [M_DIM, M_DIM+N_DIM) convert one weight row each. Both are
// DRAM-bound; merging overlaps their memory streams and saves a launch gap.
// ---------------------------------------------------------------------------
__global__ void prep_kernel(const float* __restrict__ x, const int* __restrict__ w) {
    int t = threadIdx.x;
    if ((int)blockIdx.x < M_DIM) {
        // ---- activation quant: absmax -> int8 -> bf16 (exact), swizzled ----
        int row = blockIdx.x;
        const float4* xr = reinterpret_cast<const float4*>(x + (size_t)row * K_DIM);
        float4 v[4];
        float amax = 0.0f;
#pragma unroll
        for (int i = 0; i < 4; i++) {
            v[i] = xr[t * 4 + i];
            amax = fmaxf(amax, fabsf(v[i].x));
            amax = fmaxf(amax, fabsf(v[i].y));
            amax = fmaxf(amax, fabsf(v[i].z));
            amax = fmaxf(amax, fabsf(v[i].w));
        }
        __shared__ float red[8];
        __shared__ float s_scale;
#pragma unroll
        for (int o = 16; o > 0; o >>= 1)
            amax = fmaxf(amax, __shfl_xor_sync(0xffffffffu, amax, o));
        if ((t & 31) == 0) red[t >> 5] = amax;
        __syncthreads();
        if (t == 0) {
            float m = red[0];
#pragma unroll
            for (int i = 1; i < 8; i++) m = fmaxf(m, red[i]);
            float sc = m / 127.0f;            // exact IEEE div, matches reference
            s_scale = sc;
            g_sx[row] = sc;
        }
        __syncthreads();
        float scale = s_scale;

        union { __nv_bfloat16 h[16]; int4 i4[2]; } q;
#pragma unroll
        for (int i = 0; i < 4; i++) {
            q.h[i * 4 + 0] = __float2bfloat16_rn((float)__float2int_rn(v[i].x / scale));
            q.h[i * 4 + 1] = __float2bfloat16_rn((float)__float2int_rn(v[i].y / scale));
            q.h[i * 4 + 2] = __float2bfloat16_rn((float)__float2int_rn(v[i].z / scale));
            q.h[i * 4 + 3] = __float2bfloat16_rn((float)__float2int_rn(v[i].w / scale));
        }
        int tm = row >> 7, lrow = row & 127;
        int kt = t >> 2;
        int ch0 = (t & 3) * 2;
        char* blk = (char*)g_qa + (((size_t)tm * NKT + kt) << 14) + (size_t)lrow * 128;
        *reinterpret_cast<int4*>(blk + (((ch0)     ^ (lrow & 7)) << 4)) = q.i4[0];
        *reinterpret_cast<int4*>(blk + (((ch0 + 1) ^ (lrow & 7)) << 4)) = q.i4[1];
    } else {
        // ---- weight convert: int32 -> bf16 (exact), swizzled 128-row blocks ----
        int n = (int)blockIdx.x - M_DIM;
        const int4* wr = reinterpret_cast<const int4*>(w + (size_t)n * K_DIM);
        union { __nv_bfloat16 h[16]; int4 i4[2]; } q;
#pragma unroll
        for (int i = 0; i < 4; i++) {
            int4 v = wr[t * 4 + i];
            q.h[i * 4 + 0] = __float2bfloat16_rn((float)v.x);
            q.h[i * 4 + 1] = __float2bfloat16_rn((float)v.y);
            q.h[i * 4 + 2] = __float2bfloat16_rn((float)v.z);
            q.h[i * 4 + 3] = __float2bfloat16_rn((float)v.w);
        }
        int tn = n >> 7, lrow = n & 127;
        int kt = t >> 2;
        int ch0 = (t & 3) * 2;
        char* blk = (char*)g_wb + (((size_t)tn * NKT + kt) << 14) + (size_t)lrow * 128;
        *reinterpret_cast<int4*>(blk + (((ch0)     ^ (lrow & 7)) << 4)) = q.i4[0];
        *reinterpret_cast<int4*>(blk + (((ch0 + 1) ^ (lrow & 7)) << 4)) = q.i4[1];
    }
}

// ---------------------------------------------------------------------------
// Kernel 2: bf16 HMMA GEMM — the verified R7 champion structure.
// CTA tile 128x128, 8 warps (warp tile 32x64), NS=3 bulk-copy mbarrier
// pipeline, 2 CTAs/SM.
// ---------------------------------------------------------------------------
__device__ __forceinline__ uint32_t smem_u32(const void* p) {
    uint32_t a;
    asm("{ .reg .u64 t; cvta.to.shared.u64 t, %1; cvt.u32.u64 %0, t; }" : "=r"(a) : "l"(p));
    return a;
}
__device__ __forceinline__ void mbar_init(uint32_t a, uint32_t c) {
    asm volatile("mbarrier.init.shared.b64 [%0], %1;" :: "r"(a), "r"(c) : "memory");
}
__device__ __forceinline__ void mbar_expect_tx(uint32_t a, uint32_t tx) {
    asm volatile("mbarrier.arrive.expect_tx.shared::cta.b64 _, [%0], %1;"
                 :: "r"(a), "r"(tx) : "memory");
}
__device__ __forceinline__ void bulk_g2s(uint32_t dst, const void* src, uint32_t bytes,
                                         uint32_t mbar) {
    asm volatile(
        "cp.async.bulk.shared::cta.global.mbarrier::complete_tx::bytes [%0], [%1], %2, [%3];"
        :: "r"(dst), "l"(src), "r"(bytes), "r"(mbar) : "memory");
}
__device__ __forceinline__ void mbar_wait(uint32_t a, uint32_t ph) {
    asm volatile(
        "{\n .reg .pred P;\n"
        "WL_%=:\n"
        " mbarrier.try_wait.parity.acquire.cta.shared::cta.b64 P, [%0], %1;\n"
        " @P bra.uni WD_%=;\n"
        " bra.uni WL_%=;\n"
        "WD_%=:\n}" :: "r"(a), "r"(ph) : "memory");
}
__device__ __forceinline__ void ldm_x4(uint32_t& r0, uint32_t& r1, uint32_t& r2,
                                       uint32_t& r3, uint32_t addr) {
    asm volatile("ldmatrix.sync.aligned.m8n8.x4.shared.b16 {%0,%1,%2,%3}, [%4];"
                 : "=r"(r0), "=r"(r1), "=r"(r2), "=r"(r3) : "r"(addr));
}

__global__ __launch_bounds__(256, 2) void gemm_hmma_kernel(const float* __restrict__ wscale,
                                                           const float* __restrict__ bias,
                                                           float* __restrict__ out) {
    extern __shared__ char smem[];
    uint32_t raw = smem_u32(smem);
    uint32_t sbase = (raw + 1023u) & ~1023u;
    uint32_t fullb = sbase + NS * STG;            // NS x 8B

    const int t = threadIdx.x;
    const int wid = t >> 5;
    const int lane = t & 31;
    const int warpM = wid & 3;                    // 4 warps along M (32 rows each)
    const int warpN = wid >> 2;                   // 2 warps along N (64 cols each)

    // tile decode with L2 group swizzle: tiles_m=64, tiles_n=128, GM=8
    int gid = blockIdx.x;
    int grp = gid >> 10;
    int rem = gid & 1023;
    int tm = grp * 8 + (rem & 7);
    int tn = rem >> 3;

    const char* gA = (const char*)g_qa + ((size_t)tm * NKT << 14);
    const char* gB = (const char*)g_wb + ((size_t)tn * NKT << 14);

    if (t == 0) {
#pragma unroll
        for (int s = 0; s < NS; s++) mbar_init(fullb + 8 * s, 1);
    }
    __syncthreads();

    auto issue = [&](int buf, int kt) {
        uint32_t mb = fullb + 8 * buf;
        mbar_expect_tx(mb, STG);
        bulk_g2s(sbase + buf * STG,         gA + ((size_t)kt << 14), STG_A, mb);
        bulk_g2s(sbase + buf * STG + STG_A, gB + ((size_t)kt << 14), STG_B, mb);
    };

    if (t == 0) {
        issue(0, 0);
        issue(1, 1);
    }

    float acc[2][8][4];
#pragma unroll
    for (int mf = 0; mf < 2; mf++)
#pragma unroll
        for (int nf = 0; nf < 8; nf++)
#pragma unroll
            for (int i = 0; i < 4; i++) acc[mf][nf][i] = 0.0f;

    const int seg = lane >> 3;
    const int lrow = lane & 7;
    const int a_rb = warpM * 32 + (seg & 1) * 8 + lrow;    // + mf*16
    const int b_rb = warpN * 64 + (seg & 1) * 8 + lrow;    // + nf2*16
    const int cseg = seg >> 1;

    int s = 0, ph = 0;
    for (int kt = 0; kt < NKT; kt++) {
        mbar_wait(fullb + 8 * s, ph);

        uint32_t sA = sbase + s * STG;
        uint32_t sB = sA + STG_A;

#pragma unroll
        for (int ks = 0; ks < 4; ks++) {
            const int chunk = cseg + 2 * ks;
            uint32_t a[2][4], b[8][2];
#pragma unroll
            for (int mf = 0; mf < 2; mf++) {
                int r = a_rb + mf * 16;
                ldm_x4(a[mf][0], a[mf][1], a[mf][2], a[mf][3],
                       sA + r * 128 + ((chunk ^ (r & 7)) << 4));
            }
#pragma unroll
            for (int nf2 = 0; nf2 < 4; nf2++) {
                int r = b_rb + nf2 * 16;
                uint32_t r0, r1, r2, r3;
                ldm_x4(r0, r1, r2, r3, sB + r * 128 + ((chunk ^ (r & 7)) << 4));
                b[nf2 * 2][0] = r0; b[nf2 * 2][1] = r2;
                b[nf2 * 2 + 1][0] = r1; b[nf2 * 2 + 1][1] = r3;
            }
#pragma unroll
            for (int mf = 0; mf < 2; mf++)
#pragma unroll
                for (int nf = 0; nf < 8; nf++)
                    asm volatile(
                        "mma.sync.aligned.m16n8k16.row.col.f32.bf16.bf16.f32 "
                        "{%0,%1,%2,%3}, {%4,%5,%6,%7}, {%8,%9}, {%0,%1,%2,%3};\n"
                        : "+f"(acc[mf][nf][0]), "+f"(acc[mf][nf][1]),
                          "+f"(acc[mf][nf][2]), "+f"(acc[mf][nf][3])
                        : "r"(a[mf][0]), "r"(a[mf][1]), "r"(a[mf][2]), "r"(a[mf][3]),
                          "r"(b[nf][0]), "r"(b[nf][1]));
        }

        __syncthreads();
        int nk = kt + NS - 1;
        if (t == 0 && nk < NKT) issue(s == 0 ? NS - 1 : s - 1, nk);
        if (++s == NS) { s = 0; ph ^= 1; }
    }

    // epilogue: dequant + bias (nf outer: scale/bias loaded once per column pair)
    const int tig = lane & 3;
    const int gID = lane >> 2;
    int rbase = tm * BM + warpM * 32 + gID;
    float sx00 = __ldg(g_sx + rbase);
    float sx01 = __ldg(g_sx + rbase + 8);
    float sx10 = __ldg(g_sx + rbase + 16);
    float sx11 = __ldg(g_sx + rbase + 24);
    float* orow = out + (size_t)rbase * N_DIM + tn * BN;
#pragma unroll
    for (int nf = 0; nf < 8; nf++) {
        int c = warpN * 64 + nf * 8 + tig * 2;
        float w0 = __ldg(wscale + tn * BN + c);
        float w1 = __ldg(wscale + tn * BN + c + 1);
        float b0 = __ldg(bias + tn * BN + c);
        float b1 = __ldg(bias + tn * BN + c + 1);
        float2 v;
        v.x = acc[0][nf][0] * sx00 * w0 + b0;
        v.y = acc[0][nf][1] * sx00 * w1 + b1;
        *(float2*)(orow + c) = v;
        v.x = acc[0][nf][2] * sx01 * w0 + b0;
        v.y = acc[0][nf][3] * sx01 * w1 + b1;
        *(float2*)(orow + (size_t)8 * N_DIM + c) = v;
        v.x = acc[1][nf][0] * sx10 * w0 + b0;
        v.y = acc[1][nf][1] * sx10 * w1 + b1;
        *(float2*)(orow + (size_t)16 * N_DIM + c) = v;
        v.x = acc[1][nf][2] * sx11 * w0 + b0;
        v.y = acc[1][nf][3] * sx11 * w1 + b1;
        *(float2*)(orow + (size_t)24 * N_DIM + c) = v;
    }
}

// ---------------------------------------------------------------------------
extern "C" void kernel_launch(void* const* d_in, const int* in_sizes, int n_in,
                              void* d_out, int out_size) {
    (void)in_sizes; (void)n_in; (void)out_size;
    const float* x      = (const float*)d_in[0];
    const int*   wq     = (const int*)d_in[1];
    const float* wscale = (const float*)d_in[2];
    const float* bias   = (const float*)d_in[3];
    float* out = (float*)d_out;

    prep_kernel<<<M_DIM + N_DIM, 256>>>(x, wq);

    cudaFuncSetAttribute(gemm_hmma_kernel, cudaFuncAttributeMaxDynamicSharedMemorySize,
                         SMEM_TOTAL);
    int gemm_blocks = (M_DIM / BM) * (N_DIM / BN);   // 8192
    gemm_hmma_kernel<<<gemm_blocks, 256, SMEM_TOTAL>>>(wscale, bias, out);
}

// round 14
// speedup vs baseline: 1.0971x; 1.0009x over previous
#include <cuda_runtime.h>
#include <cuda_bf16.h>
#include <cstdint>

#define M_DIM 8192
#define K_DIM 4096
#define N_DIM 16384

#define BM 128
#define BN 128
#define BKE 64                     // K elements per stage (bf16) = 128B rows
#define NKT (K_DIM / BKE)          // 64
#define NS 3
#define STG_A (BM * 128)           // 16384 bytes
#define STG_B (BN * 128)           // 16384 bytes
#define STG (STG_A + STG_B)        // 32768
#define SMEM_TOTAL (NS * STG + 1024 + 128)

// Tiled, pre-swizzled bf16 operand images (device globals; allocation-free rule)
static __device__ __align__(128) __nv_bfloat16 g_qa[(size_t)M_DIM * K_DIM];  // 64 MB
static __device__ __align__(128) __nv_bfloat16 g_wb[(size_t)N_DIM * K_DIM];  // 128 MB
static __device__ float g_sx[M_DIM];

// ---------------------------------------------------------------------------
// Kernel 1 (merged): blocks [0, M_DIM) do per-row activation quantization;
// blocks [M_DIM, M_DIM+N_DIM) convert one weight row each.
// ---------------------------------------------------------------------------
__global__ void prep_kernel(const float* __restrict__ x, const int* __restrict__ w) {
    int t = threadIdx.x;
    if ((int)blockIdx.x < M_DIM) {
        int row = blockIdx.x;
        const float4* xr = reinterpret_cast<const float4*>(x + (size_t)row * K_DIM);
        float4 v[4];
        float amax = 0.0f;
#pragma unroll
        for (int i = 0; i < 4; i++) {
            v[i] = xr[t * 4 + i];
            amax = fmaxf(amax, fabsf(v[i].x));
            amax = fmaxf(amax, fabsf(v[i].y));
            amax = fmaxf(amax, fabsf(v[i].z));
            amax = fmaxf(amax, fabsf(v[i].w));
        }
        __shared__ float red[8];
        __shared__ float s_scale;
#pragma unroll
        for (int o = 16; o > 0; o >>= 1)
            amax = fmaxf(amax, __shfl_xor_sync(0xffffffffu, amax, o));
        if ((t & 31) == 0) red[t >> 5] = amax;
        __syncthreads();
        if (t == 0) {
            float m = red[0];
#pragma unroll
            for (int i = 1; i < 8; i++) m = fmaxf(m, red[i]);
            float sc = m / 127.0f;            // exact IEEE div, matches reference
            s_scale = sc;
            g_sx[row] = sc;
        }
        __syncthreads();
        float scale = s_scale;

        union { __nv_bfloat16 h[16]; int4 i4[2]; } q;
#pragma unroll
        for (int i = 0; i < 4; i++) {
            q.h[i * 4 + 0] = __float2bfloat16_rn((float)__float2int_rn(v[i].x / scale));
            q.h[i * 4 + 1] = __float2bfloat16_rn((float)__float2int_rn(v[i].y / scale));
            q.h[i * 4 + 2] = __float2bfloat16_rn((float)__float2int_rn(v[i].z / scale));
            q.h[i * 4 + 3] = __float2bfloat16_rn((float)__float2int_rn(v[i].w / scale));
        }
        int tm = row >> 7, lrow = row & 127;
        int kt = t >> 2;
        int ch0 = (t & 3) * 2;
        char* blk = (char*)g_qa + (((size_t)tm * NKT + kt) << 14) + (size_t)lrow * 128;
        *reinterpret_cast<int4*>(blk + (((ch0)     ^ (lrow & 7)) << 4)) = q.i4[0];
        *reinterpret_cast<int4*>(blk + (((ch0 + 1) ^ (lrow & 7)) << 4)) = q.i4[1];
    } else {
        int n = (int)blockIdx.x - M_DIM;
        const int4* wr = reinterpret_cast<const int4*>(w + (size_t)n * K_DIM);
        union { __nv_bfloat16 h[16]; int4 i4[2]; } q;
#pragma unroll
        for (int i = 0; i < 4; i++) {
            int4 v = wr[t * 4 + i];
            q.h[i * 4 + 0] = __float2bfloat16_rn((float)v.x);
            q.h[i * 4 + 1] = __float2bfloat16_rn((float)v.y);
            q.h[i * 4 + 2] = __float2bfloat16_rn((float)v.z);
            q.h[i * 4 + 3] = __float2bfloat16_rn((float)v.w);
        }
        int tn = n >> 7, lrow = n & 127;
        int kt = t >> 2;
        int ch0 = (t & 3) * 2;
        char* blk = (char*)g_wb + (((size_t)tn * NKT + kt) << 14) + (size_t)lrow * 128;
        *reinterpret_cast<int4*>(blk + (((ch0)     ^ (lrow & 7)) << 4)) = q.i4[0];
        *reinterpret_cast<int4*>(blk + (((ch0 + 1) ^ (lrow & 7)) << 4)) = q.i4[1];
    }
}

// ---------------------------------------------------------------------------
// Kernel 2: bf16 HMMA GEMM (R7 champion structure) with per-warp ks-order
// staggering: warpN=1 warps traverse the 4 k16-slices in reverse so the two
// warps sharing each SMSP are always in opposite LDSM/HMMA phases.
// Integer-exact => reordering K accumulation is bit-identical.
// ---------------------------------------------------------------------------
__device__ __forceinline__ uint32_t smem_u32(const void* p) {
    uint32_t a;
    asm("{ .reg .u64 t; cvta.to.shared.u64 t, %1; cvt.u32.u64 %0, t; }" : "=r"(a) : "l"(p));
    return a;
}
__device__ __forceinline__ void mbar_init(uint32_t a, uint32_t c) {
    asm volatile("mbarrier.init.shared.b64 [%0], %1;" :: "r"(a), "r"(c) : "memory");
}
__device__ __forceinline__ void mbar_expect_tx(uint32_t a, uint32_t tx) {
    asm volatile("mbarrier.arrive.expect_tx.shared::cta.b64 _, [%0], %1;"
                 :: "r"(a), "r"(tx) : "memory");
}
__device__ __forceinline__ void bulk_g2s(uint32_t dst, const void* src, uint32_t bytes,
                                         uint32_t mbar) {
    asm volatile(
        "cp.async.bulk.shared::cta.global.mbarrier::complete_tx::bytes [%0], [%1], %2, [%3];"
        :: "r"(dst), "l"(src), "r"(bytes), "r"(mbar) : "memory");
}
__device__ __forceinline__ void mbar_wait(uint32_t a, uint32_t ph) {
    asm volatile(
        "{\n .reg .pred P;\n"
        "WL_%=:\n"
        " mbarrier.try_wait.parity.acquire.cta.shared::cta.b64 P, [%0], %1;\n"
        " @P bra.uni WD_%=;\n"
        " bra.uni WL_%=;\n"
        "WD_%=:\n}" :: "r"(a), "r"(ph) : "memory");
}
__device__ __forceinline__ void ldm_x4(uint32_t& r0, uint32_t& r1, uint32_t& r2,
                                       uint32_t& r3, uint32_t addr) {
    asm volatile("ldmatrix.sync.aligned.m8n8.x4.shared.b16 {%0,%1,%2,%3}, [%4];"
                 : "=r"(r0), "=r"(r1), "=r"(r2), "=r"(r3) : "r"(addr));
}

__global__ __launch_bounds__(256, 2) void gemm_hmma_kernel(const float* __restrict__ wscale,
                                                           const float* __restrict__ bias,
                                                           float* __restrict__ out) {
    extern __shared__ char smem[];
    uint32_t raw = smem_u32(smem);
    uint32_t sbase = (raw + 1023u) & ~1023u;
    uint32_t fullb = sbase + NS * STG;            // NS x 8B

    const int t = threadIdx.x;
    const int wid = t >> 5;
    const int lane = t & 31;
    const int warpM = wid & 3;                    // 4 warps along M (32 rows each)
    const int warpN = wid >> 2;                   // 2 warps along N (64 cols each)

    // tile decode with L2 group swizzle: tiles_m=64, tiles_n=128, GM=8
    int gid = blockIdx.x;
    int grp = gid >> 10;
    int rem = gid & 1023;
    int tm = grp * 8 + (rem & 7);
    int tn = rem >> 3;

    const char* gA = (const char*)g_qa + ((size_t)tm * NKT << 14);
    const char* gB = (const char*)g_wb + ((size_t)tn * NKT << 14);

    if (t == 0) {
#pragma unroll
        for (int s = 0; s < NS; s++) mbar_init(fullb + 8 * s, 1);
    }
    __syncthreads();

    auto issue = [&](int buf, int kt) {
        uint32_t mb = fullb + 8 * buf;
        mbar_expect_tx(mb, STG);
        bulk_g2s(sbase + buf * STG,         gA + ((size_t)kt << 14), STG_A, mb);
        bulk_g2s(sbase + buf * STG + STG_A, gB + ((size_t)kt << 14), STG_B, mb);
    };

    if (t == 0) {
        issue(0, 0);
        issue(1, 1);
    }

    float acc[2][8][4];
#pragma unroll
    for (int mf = 0; mf < 2; mf++)
#pragma unroll
        for (int nf = 0; nf < 8; nf++)
#pragma unroll
            for (int i = 0; i < 4; i++) acc[mf][nf][i] = 0.0f;

    const int seg = lane >> 3;
    const int lrow = lane & 7;
    const int a_rb = warpM * 32 + (seg & 1) * 8 + lrow;    // + mf*16
    const int b_rb = warpN * 64 + (seg & 1) * 8 + lrow;    // + nf2*16
    const int cseg = seg >> 1;
    const bool rev = (warpN != 0);   // SMSP = wid&3 = warpM; its 2 warps differ in warpN

    // one k16-slice: ldmatrix fragments + 16 HMMAs
    auto do_ks = [&](uint32_t sA, uint32_t sB, int ks) {
        const int chunk = cseg + 2 * ks;
        uint32_t a[2][4], b[8][2];
#pragma unroll
        for (int mf = 0; mf < 2; mf++) {
            int r = a_rb + mf * 16;
            ldm_x4(a[mf][0], a[mf][1], a[mf][2], a[mf][3],
                   sA + r * 128 + ((chunk ^ (r & 7)) << 4));
        }
#pragma unroll
        for (int nf2 = 0; nf2 < 4; nf2++) {
            int r = b_rb + nf2 * 16;
            uint32_t r0, r1, r2, r3;
            ldm_x4(r0, r1, r2, r3, sB + r * 128 + ((chunk ^ (r & 7)) << 4));
            b[nf2 * 2][0] = r0; b[nf2 * 2][1] = r2;
            b[nf2 * 2 + 1][0] = r1; b[nf2 * 2 + 1][1] = r3;
        }
#pragma unroll
        for (int mf = 0; mf < 2; mf++)
#pragma unroll
            for (int nf = 0; nf < 8; nf++)
                asm volatile(
                    "mma.sync.aligned.m16n8k16.row.col.f32.bf16.bf16.f32 "
                    "{%0,%1,%2,%3}, {%4,%5,%6,%7}, {%8,%9}, {%0,%1,%2,%3};\n"
                    : "+f"(acc[mf][nf][0]), "+f"(acc[mf][nf][1]),
                      "+f"(acc[mf][nf][2]), "+f"(acc[mf][nf][3])
                    : "r"(a[mf][0]), "r"(a[mf][1]), "r"(a[mf][2]), "r"(a[mf][3]),
                      "r"(b[nf][0]), "r"(b[nf][1]));
    };

    int s = 0, ph = 0;
    for (int kt = 0; kt < NKT; kt++) {
        mbar_wait(fullb + 8 * s, ph);

        uint32_t sA = sbase + s * STG;
        uint32_t sB = sA + STG_A;

        // ks-order stagger: warpN=1 runs 3,2,1,0 (compile-time addresses in
        // both branches; integer-exact so order is numerically irrelevant)
        if (rev) {
#pragma unroll
            for (int kk = 3; kk >= 0; kk--) do_ks(sA, sB, kk);
        } else {
#pragma unroll
            for (int kk = 0; kk < 4; kk++) do_ks(sA, sB, kk);
        }

        __syncthreads();
        int nk = kt + NS - 1;
        if (t == 0 && nk < NKT) issue(s == 0 ? NS - 1 : s - 1, nk);
        if (++s == NS) { s = 0; ph ^= 1; }
    }

    // epilogue: dequant + bias (nf outer: scale/bias loaded once per column pair)
    const int tig = lane & 3;
    const int gID = lane >> 2;
    int rbase = tm * BM + warpM * 32 + gID;
    float sx00 = __ldg(g_sx + rbase);
    float sx01 = __ldg(g_sx + rbase + 8);
    float sx10 = __ldg(g_sx + rbase + 16);
    float sx11 = __ldg(g_sx + rbase + 24);
    float* orow = out + (size_t)rbase * N_DIM + tn * BN;
#pragma unroll
    for (int nf = 0; nf < 8; nf++) {
        int c = warpN * 64 + nf * 8 + tig * 2;
        float w0 = __ldg(wscale + tn * BN + c);
        float w1 = __ldg(wscale + tn * BN + c + 1);
        float b0 = __ldg(bias + tn * BN + c);
        float b1 = __ldg(bias + tn * BN + c + 1);
        float2 v;
        v.x = acc[0][nf][0] * sx00 * w0 + b0;
        v.y = acc[0][nf][1] * sx00 * w1 + b1;
        *(float2*)(orow + c) = v;
        v.x = acc[0][nf][2] * sx01 * w0 + b0;
        v.y = acc[0][nf][3] * sx01 * w1 + b1;
        *(float2*)(orow + (size_t)8 * N_DIM + c) = v;
        v.x = acc[1][nf][0] * sx10 * w0 + b0;
        v.y = acc[1][nf][1] * sx10 * w1 + b1;
        *(float2*)(orow + (size_t)16 * N_DIM + c) = v;
        v.x = acc[1][nf][2] * sx11 * w0 + b0;
        v.y = acc[1][nf][3] * sx11 * w1 + b1;
        *(float2*)(orow + (size_t)24 * N_DIM + c) = v;
    }
}

// ---------------------------------------------------------------------------
extern "C" void kernel_launch(void* const* d_in, const int* in_sizes, int n_in,
                              void* d_out, int out_size) {
    (void)in_sizes; (void)n_in; (void)out_size;
    const float* x      = (const float*)d_in[0];
    const int*   wq     = (const int*)d_in[1];
    const float* wscale = (const float*)d_in[2];
    const float* bias   = (const float*)d_in[3];
    float* out = (float*)d_out;

    prep_kernel<<<M_DIM + N_DIM, 256>>>(x, wq);

    cudaFuncSetAttribute(gemm_hmma_kernel, cudaFuncAttributeMaxDynamicSharedMemorySize,
                         SMEM_TOTAL);
    int gemm_blocks = (M_DIM / BM) * (N_DIM / BN);   // 8192
    gemm_hmma_kernel<<<gemm_blocks, 256, SMEM_TOTAL>>>(wscale, bias, out);
}

// round 15
// speedup vs baseline: 1.1024x; 1.0048x over previous
#include <cuda_runtime.h>
#include <cuda_bf16.h>
#include <cstdint>

#define M_DIM 8192
#define K_DIM 4096
#define N_DIM 16384

#define BM 128
#define BN 128
#define BKE 64                     // K elements per stage (bf16) = 128B rows
#define NKT (K_DIM / BKE)          // 64
#define NS 3
#define STG_A (BM * 128)           // 16384 bytes
#define STG_B (BN * 128)           // 16384 bytes
#define STG (STG_A + STG_B)        // 32768
#define SMEM_TOTAL (NS * STG + 1024 + 128)

// Tiled, pre-swizzled bf16 operand images (device globals; allocation-free rule)
static __device__ __align__(128) __nv_bfloat16 g_qa[(size_t)M_DIM * K_DIM];  // 64 MB
static __device__ __align__(128) __nv_bfloat16 g_wb[(size_t)N_DIM * K_DIM];  // 128 MB
static __device__ float g_sx[M_DIM];

// ---------------------------------------------------------------------------
// Kernel 1 (merged): blocks [0, M_DIM) do per-row activation quantization;
// blocks [M_DIM, M_DIM+N_DIM) convert one weight row each.
// ---------------------------------------------------------------------------
__global__ void prep_kernel(const float* __restrict__ x, const int* __restrict__ w) {
    int t = threadIdx.x;
    if ((int)blockIdx.x < M_DIM) {
        int row = blockIdx.x;
        const float4* xr = reinterpret_cast<const float4*>(x + (size_t)row * K_DIM);
        float4 v[4];
        float amax = 0.0f;
#pragma unroll
        for (int i = 0; i < 4; i++) {
            v[i] = xr[t * 4 + i];
            amax = fmaxf(amax, fabsf(v[i].x));
            amax = fmaxf(amax, fabsf(v[i].y));
            amax = fmaxf(amax, fabsf(v[i].z));
            amax = fmaxf(amax, fabsf(v[i].w));
        }
        __shared__ float red[8];
        __shared__ float s_scale;
#pragma unroll
        for (int o = 16; o > 0; o >>= 1)
            amax = fmaxf(amax, __shfl_xor_sync(0xffffffffu, amax, o));
        if ((t & 31) == 0) red[t >> 5] = amax;
        __syncthreads();
        if (t == 0) {
            float m = red[0];
#pragma unroll
            for (int i = 1; i < 8; i++) m = fmaxf(m, red[i]);
            float sc = m / 127.0f;            // exact IEEE div, matches reference
            s_scale = sc;
            g_sx[row] = sc;
        }
        __syncthreads();
        float scale = s_scale;

        union { __nv_bfloat16 h[16]; int4 i4[2]; } q;
#pragma unroll
        for (int i = 0; i < 4; i++) {
            q.h[i * 4 + 0] = __float2bfloat16_rn((float)__float2int_rn(v[i].x / scale));
            q.h[i * 4 + 1] = __float2bfloat16_rn((float)__float2int_rn(v[i].y / scale));
            q.h[i * 4 + 2] = __float2bfloat16_rn((float)__float2int_rn(v[i].z / scale));
            q.h[i * 4 + 3] = __float2bfloat16_rn((float)__float2int_rn(v[i].w / scale));
        }
        int tm = row >> 7, lrow = row & 127;
        int kt = t >> 2;
        int ch0 = (t & 3) * 2;
        char* blk = (char*)g_qa + (((size_t)tm * NKT + kt) << 14) + (size_t)lrow * 128;
        *reinterpret_cast<int4*>(blk + (((ch0)     ^ (lrow & 7)) << 4)) = q.i4[0];
        *reinterpret_cast<int4*>(blk + (((ch0 + 1) ^ (lrow & 7)) << 4)) = q.i4[1];
    } else {
        int n = (int)blockIdx.x - M_DIM;
        const int4* wr = reinterpret_cast<const int4*>(w + (size_t)n * K_DIM);
        union { __nv_bfloat16 h[16]; int4 i4[2]; } q;
#pragma unroll
        for (int i = 0; i < 4; i++) {
            int4 v = wr[t * 4 + i];
            q.h[i * 4 + 0] = __float2bfloat16_rn((float)v.x);
            q.h[i * 4 + 1] = __float2bfloat16_rn((float)v.y);
            q.h[i * 4 + 2] = __float2bfloat16_rn((float)v.z);
            q.h[i * 4 + 3] = __float2bfloat16_rn((float)v.w);
        }
        int tn = n >> 7, lrow = n & 127;
        int kt = t >> 2;
        int ch0 = (t & 3) * 2;
        char* blk = (char*)g_wb + (((size_t)tn * NKT + kt) << 14) + (size_t)lrow * 128;
        *reinterpret_cast<int4*>(blk + (((ch0)     ^ (lrow & 7)) << 4)) = q.i4[0];
        *reinterpret_cast<int4*>(blk + (((ch0 + 1) ^ (lrow & 7)) << 4)) = q.i4[1];
    }
}

// ---------------------------------------------------------------------------
// Kernel 2: bf16 HMMA GEMM (R7 champion structure) with A-fragment-only
// double buffering across k16-slices: +8 registers (fits the 128-reg cap,
// unlike R8's full double buffer), removes the 2 A-LDSMs from each
// next-slice critical path. Numerically exact.
// ---------------------------------------------------------------------------
__device__ __forceinline__ uint32_t smem_u32(const void* p) {
    uint32_t a;
    asm("{ .reg .u64 t; cvta.to.shared.u64 t, %1; cvt.u32.u64 %0, t; }" : "=r"(a) : "l"(p));
    return a;
}
__device__ __forceinline__ void mbar_init(uint32_t a, uint32_t c) {
    asm volatile("mbarrier.init.shared.b64 [%0], %1;" :: "r"(a), "r"(c) : "memory");
}
__device__ __forceinline__ void mbar_expect_tx(uint32_t a, uint32_t tx) {
    asm volatile("mbarrier.arrive.expect_tx.shared::cta.b64 _, [%0], %1;"
                 :: "r"(a), "r"(tx) : "memory");
}
__device__ __forceinline__ void bulk_g2s(uint32_t dst, const void* src, uint32_t bytes,
                                         uint32_t mbar) {
    asm volatile(
        "cp.async.bulk.shared::cta.global.mbarrier::complete_tx::bytes [%0], [%1], %2, [%3];"
        :: "r"(dst), "l"(src), "r"(bytes), "r"(mbar) : "memory");
}
__device__ __forceinline__ void mbar_wait(uint32_t a, uint32_t ph) {
    asm volatile(
        "{\n .reg .pred P;\n"
        "WL_%=:\n"
        " mbarrier.try_wait.parity.acquire.cta.shared::cta.b64 P, [%0], %1;\n"
        " @P bra.uni WD_%=;\n"
        " bra.uni WL_%=;\n"
        "WD_%=:\n}" :: "r"(a), "r"(ph) : "memory");
}
__device__ __forceinline__ void ldm_x4(uint32_t& r0, uint32_t& r1, uint32_t& r2,
                                       uint32_t& r3, uint32_t addr) {
    asm volatile("ldmatrix.sync.aligned.m8n8.x4.shared.b16 {%0,%1,%2,%3}, [%4];"
                 : "=r"(r0), "=r"(r1), "=r"(r2), "=r"(r3) : "r"(addr));
}

__global__ __launch_bounds__(256, 2) void gemm_hmma_kernel(const float* __restrict__ wscale,
                                                           const float* __restrict__ bias,
                                                           float* __restrict__ out) {
    extern __shared__ char smem[];
    uint32_t raw = smem_u32(smem);
    uint32_t sbase = (raw + 1023u) & ~1023u;
    uint32_t fullb = sbase + NS * STG;            // NS x 8B

    const int t = threadIdx.x;
    const int wid = t >> 5;
    const int lane = t & 31;
    const int warpM = wid & 3;                    // 4 warps along M (32 rows each)
    const int warpN = wid >> 2;                   // 2 warps along N (64 cols each)

    // tile decode with L2 group swizzle: tiles_m=64, tiles_n=128, GM=8
    int gid = blockIdx.x;
    int grp = gid >> 10;
    int rem = gid & 1023;
    int tm = grp * 8 + (rem & 7);
    int tn = rem >> 3;

    const char* gA = (const char*)g_qa + ((size_t)tm * NKT << 14);
    const char* gB = (const char*)g_wb + ((size_t)tn * NKT << 14);

    if (t == 0) {
#pragma unroll
        for (int s = 0; s < NS; s++) mbar_init(fullb + 8 * s, 1);
    }
    __syncthreads();

    auto issue = [&](int buf, int kt) {
        uint32_t mb = fullb + 8 * buf;
        mbar_expect_tx(mb, STG);
        bulk_g2s(sbase + buf * STG,         gA + ((size_t)kt << 14), STG_A, mb);
        bulk_g2s(sbase + buf * STG + STG_A, gB + ((size_t)kt << 14), STG_B, mb);
    };

    if (t == 0) {
        issue(0, 0);
        issue(1, 1);
    }

    float acc[2][8][4];
#pragma unroll
    for (int mf = 0; mf < 2; mf++)
#pragma unroll
        for (int nf = 0; nf < 8; nf++)
#pragma unroll
            for (int i = 0; i < 4; i++) acc[mf][nf][i] = 0.0f;

    const int seg = lane >> 3;
    const int lrow = lane & 7;
    const int a_rb = warpM * 32 + (seg & 1) * 8 + lrow;    // + mf*16
    const int b_rb = warpN * 64 + (seg & 1) * 8 + lrow;    // + nf2*16
    const int cseg = seg >> 1;

    int s = 0, ph = 0;
    for (int kt = 0; kt < NKT; kt++) {
        mbar_wait(fullb + 8 * s, ph);

        uint32_t sA = sbase + s * STG;
        uint32_t sB = sA + STG_A;

        // A-fragment double buffer (+8 regs only; B stays single-buffered)
        uint32_t af[2][2][4];
        {
            const int chunk = cseg;                        // ks = 0
#pragma unroll
            for (int mf = 0; mf < 2; mf++) {
                int r = a_rb + mf * 16;
                ldm_x4(af[0][mf][0], af[0][mf][1], af[0][mf][2], af[0][mf][3],
                       sA + r * 128 + ((chunk ^ (r & 7)) << 4));
            }
        }
#pragma unroll
        for (int ks = 0; ks < 4; ks++) {
            const int cur = ks & 1, nxt = cur ^ 1;
            const int chunk = cseg + 2 * ks;
            uint32_t b[8][2];
            // B loads for the current slice
#pragma unroll
            for (int nf2 = 0; nf2 < 4; nf2++) {
                int r = b_rb + nf2 * 16;
                uint32_t r0, r1, r2, r3;
                ldm_x4(r0, r1, r2, r3, sB + r * 128 + ((chunk ^ (r & 7)) << 4));
                b[nf2 * 2][0] = r0; b[nf2 * 2][1] = r2;
                b[nf2 * 2 + 1][0] = r1; b[nf2 * 2 + 1][1] = r3;
            }
            // A prefetch for the next slice (off the next critical path)
            if (ks < 3) {
                const int nchunk = cseg + 2 * (ks + 1);
#pragma unroll
                for (int mf = 0; mf < 2; mf++) {
                    int r = a_rb + mf * 16;
                    ldm_x4(af[nxt][mf][0], af[nxt][mf][1], af[nxt][mf][2], af[nxt][mf][3],
                           sA + r * 128 + ((nchunk ^ (r & 7)) << 4));
                }
            }
#pragma unroll
            for (int mf = 0; mf < 2; mf++)
#pragma unroll
                for (int nf = 0; nf < 8; nf++)
                    asm volatile(
                        "mma.sync.aligned.m16n8k16.row.col.f32.bf16.bf16.f32 "
                        "{%0,%1,%2,%3}, {%4,%5,%6,%7}, {%8,%9}, {%0,%1,%2,%3};\n"
                        : "+f"(acc[mf][nf][0]), "+f"(acc[mf][nf][1]),
                          "+f"(acc[mf][nf][2]), "+f"(acc[mf][nf][3])
                        : "r"(af[cur][mf][0]), "r"(af[cur][mf][1]),
                          "r"(af[cur][mf][2]), "r"(af[cur][mf][3]),
                          "r"(b[nf][0]), "r"(b[nf][1]));
        }

        __syncthreads();
        int nk = kt + NS - 1;
        if (t == 0 && nk < NKT) issue(s == 0 ? NS - 1 : s - 1, nk);
        if (++s == NS) { s = 0; ph ^= 1; }
    }

    // epilogue: dequant + bias (nf outer: scale/bias loaded once per column pair)
    const int tig = lane & 3;
    const int gID = lane >> 2;
    int rbase = tm * BM + warpM * 32 + gID;
    float sx00 = __ldg(g_sx + rbase);
    float sx01 = __ldg(g_sx + rbase + 8);
    float sx10 = __ldg(g_sx + rbase + 16);
    float sx11 = __ldg(g_sx + rbase + 24);
    float* orow = out + (size_t)rbase * N_DIM + tn * BN;
#pragma unroll
    for (int nf = 0; nf < 8; nf++) {
        int c = warpN * 64 + nf * 8 + tig * 2;
        float w0 = __ldg(wscale + tn * BN + c);
        float w1 = __ldg(wscale + tn * BN + c + 1);
        float b0 = __ldg(bias + tn * BN + c);
        float b1 = __ldg(bias + tn * BN + c + 1);
        float2 v;
        v.x = acc[0][nf][0] * sx00 * w0 + b0;
        v.y = acc[0][nf][1] * sx00 * w1 + b1;
        *(float2*)(orow + c) = v;
        v.x = acc[0][nf][2] * sx01 * w0 + b0;
        v.y = acc[0][nf][3] * sx01 * w1 + b1;
        *(float2*)(orow + (size_t)8 * N_DIM + c) = v;
        v.x = acc[1][nf][0] * sx10 * w0 + b0;
        v.y = acc[1][nf][1] * sx10 * w1 + b1;
        *(float2*)(orow + (size_t)16 * N_DIM + c) = v;
        v.x = acc[1][nf][2] * sx11 * w0 + b0;
        v.y = acc[1][nf][3] * sx11 * w1 + b1;
        *(float2*)(orow + (size_t)24 * N_DIM + c) = v;
    }
}

// ---------------------------------------------------------------------------
extern "C" void kernel_launch(void* const* d_in, const int* in_sizes, int n_in,
                              void* d_out, int out_size) {
    (void)in_sizes; (void)n_in; (void)out_size;
    const float* x      = (const float*)d_in[0];
    const int*   wq     = (const int*)d_in[1];
    const float* wscale = (const float*)d_in[2];
    const float* bias   = (const float*)d_in[3];
    float* out = (float*)d_out;

    prep_kernel<<<M_DIM + N_DIM, 256>>>(x, wq);

    cudaFuncSetAttribute(gemm_hmma_kernel, cudaFuncAttributeMaxDynamicSharedMemorySize,
                         SMEM_TOTAL);
    int gemm_blocks = (M_DIM / BM) * (N_DIM / BN);   // 8192
    gemm_hmma_kernel<<<gemm_blocks, 256, SMEM_TOTAL>>>(wscale, bias, out);
}